// round 16
// baseline (speedup 1.0000x reference)
#include <cuda_runtime.h>
#include <cuda_bf16.h>
#include <cuda_fp16.h>
#include <math.h>
#include <stdint.h>

#define D_MODEL 1024
#define NHEAD   16
#define BATCH   4
#define SEQ     2048
#define EDIM    64
#define M_ROWS  (BATCH * SEQ)   // 8192
#define NPCTA   296              // persistent grid: 2 CTAs x 148 SMs (safe lower bound)

// ---------------------------------------------------------------------------
// Scratch (static device globals: allocation-guard safe)
// ---------------------------------------------------------------------------
__device__ float g_mask_bias[BATCH * SEQ];
__device__ unsigned int g_ctr[4];                           // tile counters

__device__ unsigned short g_x16[M_ROWS * D_MODEL];          // fp16 x
__device__ unsigned short g_wq16[3 * D_MODEL * D_MODEL];    // fp16 Wqkv
__device__ unsigned short g_kqv16[M_ROWS * 3 * D_MODEL];    // fp16 kqv
__device__ unsigned short g_y16[M_ROWS * D_MODEL];          // fp16 attn out
__device__ unsigned short g_wp16[D_MODEL * D_MODEL];        // fp16 Wproj

// ---------------------------------------------------------------------------
// PTX helpers (standard PTX only — compute_103 virtual arch: no tcgen05)
// ---------------------------------------------------------------------------
__device__ __forceinline__ uint32_t smem_u32(const void* p) {
    uint32_t a;
    asm("{ .reg .u64 t; cvta.to.shared.u64 t, %1; cvt.u32.u64 %0, t; }"
        : "=r"(a) : "l"(p));
    return a;
}

#define LDSM_X4(r0, r1, r2, r3, addr) \
    asm volatile("ldmatrix.sync.aligned.m8n8.x4.shared.b16 {%0,%1,%2,%3}, [%4];" \
        : "=r"(r0), "=r"(r1), "=r"(r2), "=r"(r3) : "r"(addr))

#define LDSM_X4_T(r0, r1, r2, r3, addr) \
    asm volatile("ldmatrix.sync.aligned.m8n8.x4.trans.shared.b16 {%0,%1,%2,%3}, [%4];" \
        : "=r"(r0), "=r"(r1), "=r"(r2), "=r"(r3) : "r"(addr))

#define MMA_F16(d, a, b) \
    asm volatile("mma.sync.aligned.m16n8k16.row.col.f32.f16.f16.f32 " \
        "{%0,%1,%2,%3}, {%4,%5,%6,%7}, {%8,%9}, {%0,%1,%2,%3};" \
        : "+f"((d)[0]), "+f"((d)[1]), "+f"((d)[2]), "+f"((d)[3]) \
        : "r"((a)[0]), "r"((a)[1]), "r"((a)[2]), "r"((a)[3]), \
          "r"((b)[0]), "r"((b)[1]))

#define CP_ASYNC16(saddr, gptr) \
    asm volatile("cp.async.cg.shared.global [%0], [%1], 16;" \
        :: "r"(saddr), "l"(gptr))
#define CP_COMMIT() asm volatile("cp.async.commit_group;" ::: "memory")
#define CP_WAIT1()  asm volatile("cp.async.wait_group 1;" ::: "memory")
#define CP_WAIT0()  asm volatile("cp.async.wait_group 0;" ::: "memory")

#define CVT_F16X2(out, lo, hi) \
    asm("cvt.rn.f16x2.f32 %0, %1, %2;" : "=r"(out) : "f"(hi), "f"(lo))

// ---------------------------------------------------------------------------
// Mask normalization + counter zeroing (runs first each replay; stream order
// guarantees counters are zero before persistent kernels consume them)
// ---------------------------------------------------------------------------
__global__ void mask_norm_kernel(const void* __restrict__ mask_raw,
                                 float* __restrict__ mb,
                                 unsigned int* __restrict__ ctr)
{
    int i = blockIdx.x * blockDim.x + threadIdx.x;
    if (i == 0) { ctr[0] = 0; ctr[1] = 0; ctr[2] = 0; ctr[3] = 0; }
    const int n = BATCH * SEQ;
    if (i >= n) return;
    const unsigned int w0 = *(const unsigned int*)mask_raw;
    bool t;
    if (w0 == 0x3F800000u) {
        t = (((const float*)mask_raw)[i] != 0.0f);
    } else if (w0 == 1u) {
        t = (((const int*)mask_raw)[i] != 0);
    } else {
        t = (((const unsigned char*)mask_raw)[i] != 0);
    }
    mb[i] = t ? 0.0f : -1e9f;
}

// ---------------------------------------------------------------------------
// Fused fp32 -> fp16 converts for x, Wqkv, Wproj (one launch)
// ---------------------------------------------------------------------------
__global__ void cvt_all_kernel(const float* __restrict__ x,
                               const float* __restrict__ wq,
                               const float* __restrict__ wp,
                               unsigned short* __restrict__ x16,
                               unsigned short* __restrict__ wq16,
                               unsigned short* __restrict__ wp16)
{
    const int n0 = M_ROWS * D_MODEL / 4;
    const int n1 = 3 * D_MODEL * D_MODEL / 4;
    const int n2 = D_MODEL * D_MODEL / 4;
    const int total = n0 + n1 + n2;
    for (int i = blockIdx.x * blockDim.x + threadIdx.x; i < total;
         i += gridDim.x * blockDim.x) {
        const float* in; unsigned short* out; int j;
        if (i < n0)           { in = x;  out = x16;  j = i; }
        else if (i < n0 + n1) { in = wq; out = wq16; j = i - n0; }
        else                  { in = wp; out = wp16; j = i - n0 - n1; }
        float4 v = ((const float4*)in)[j];
        uint2 o;
        CVT_F16X2(o.x, v.x, v.y);
        CVT_F16X2(o.y, v.z, v.w);
        ((uint2*)out)[j] = o;
    }
}

// ---------------------------------------------------------------------------
// Persistent mma.sync fp16 GEMM: C = A[M,K] @ B[N,K]^T + bias[N]
// CTA tile 128x128, BK=64, 256 threads, XOR-swizzled smem, 3-stage cp.async.
// Tiles pulled dynamically from a global counter (removes wave quantization).
// ---------------------------------------------------------------------------
#define GARR 16384                    // 128 rows x 128B
#define STGB 32768                    // A + B

// 128B-row swizzle: (row, 16B-chunk c in 0..7)
#define ASWZ(r, c) ((uint32_t)((r) * 128 + ((((c) ^ ((r) & 7))) << 4)))

template <bool F16_OUT>
__global__ __launch_bounds__(256, 2) void mma_gemm_f16_kernel(
    const unsigned short* __restrict__ A16,
    const unsigned short* __restrict__ B16,
    const float* __restrict__ bias, float* __restrict__ C,
    unsigned short* __restrict__ Cf16,
    int N, int K, int n_tiles, int gx, unsigned int* __restrict__ ctr)
{
    extern __shared__ char gsm[];
    __shared__ int s_t;
    const uint32_t sb = smem_u32(gsm);
    const int tid  = threadIdx.x;
    const int lane = tid & 31;
    const int w    = tid >> 5;
    const int wm   = (w & 3) * 32;
    const int wn   = (w >> 2) * 64;
    const int lr = lane & 7;
    const int lh = (lane >> 3) & 1;
    const int lk = lane >> 4;
    const int gr = lane >> 2;
    const int gc = (lane & 3) * 2;
    const int NK = K / 64;

    for (;;) {
        __syncthreads();                       // previous tile done with smem
        if (tid == 0) s_t = (int)atomicAdd(ctr, 1u);
        __syncthreads();
        const int t = s_t;
        if (t >= n_tiles) return;
        const int bm = (t / gx) * 128;
        const int bn = (t % gx) * 128;

        float acc[2][8][4];
#pragma unroll
        for (int mi = 0; mi < 2; mi++)
#pragma unroll
            for (int nj = 0; nj < 8; nj++)
#pragma unroll
                for (int q = 0; q < 4; q++) acc[mi][nj][q] = 0.0f;

        auto load_stage = [&](int kt, int stage) {
            const int k0 = kt * 64;
            const uint32_t so = sb + stage * STGB;
#pragma unroll
            for (int i = 0; i < 4; i++) {
                const int chunk = tid + i * 256;      // 0..1023
                const int r  = chunk >> 3;
                const int c  = chunk & 7;
                const uint32_t sa = ASWZ(r, c);
                const size_t goA = (size_t)(bm + r) * K + k0 + c * 8;
                const size_t goB = (size_t)(bn + r) * K + k0 + c * 8;
                CP_ASYNC16(so + sa,        A16 + goA);
                CP_ASYNC16(so + GARR + sa, B16 + goB);
            }
        };

        load_stage(0, 0); CP_COMMIT();
        load_stage(1, 1); CP_COMMIT();

        int st = 0;
        for (int kt = 0; kt < NK; kt++) {
            if (kt == NK - 1) CP_WAIT0(); else CP_WAIT1();
            __syncthreads();
            if (kt + 2 < NK) { load_stage(kt + 2, (kt + 2) % 3); CP_COMMIT(); }

            const uint32_t so = sb + st * STGB;
            const uint32_t aB = so;
            const uint32_t bB = so + GARR;

#pragma unroll
            for (int kk = 0; kk < 4; kk++) {
                const int ck = (kk << 1) | lk;
                uint32_t af[2][4];
#pragma unroll
                for (int mi = 0; mi < 2; mi++) {
                    const int arow = wm + mi * 16 + lr + lh * 8;
                    LDSM_X4(af[mi][0], af[mi][1], af[mi][2], af[mi][3],
                            aB + ASWZ(arow, ck));
                }
#pragma unroll
                for (int jp = 0; jp < 4; jp++) {
                    const int brow = wn + jp * 16 + lr + lh * 8;
                    uint32_t t0, t1, t2, t3;
                    uint32_t bf[2][2];
                    LDSM_X4(t0, t1, t2, t3, bB + ASWZ(brow, ck));
                    bf[0][0] = t0; bf[1][0] = t1; bf[0][1] = t2; bf[1][1] = t3;
#pragma unroll
                    for (int mi = 0; mi < 2; mi++)
#pragma unroll
                        for (int j = 0; j < 2; j++)
                            MMA_F16(acc[mi][jp * 2 + j], af[mi], bf[j]);
                }
            }
            st++; if (st == 3) st = 0;
        }

        // Epilogue (registers only — no smem)
#pragma unroll
        for (int mi = 0; mi < 2; mi++) {
#pragma unroll
            for (int half = 0; half < 2; half++) {
                const int row = bm + wm + mi * 16 + gr + half * 8;
#pragma unroll
                for (int nj = 0; nj < 8; nj++) {
                    const int col = bn + wn + nj * 8 + gc;
                    float v0 = acc[mi][nj][half * 2 + 0] + bias[col];
                    float v1 = acc[mi][nj][half * 2 + 1] + bias[col + 1];
                    if (F16_OUT) {
                        uint32_t hh;
                        CVT_F16X2(hh, v0, v1);
                        *(uint32_t*)(Cf16 + (size_t)row * N + col) = hh;
                    } else {
                        float2 o; o.x = v0; o.y = v1;
                        *(float2*)(C + (size_t)row * N + col) = o;
                    }
                }
            }
        }
    }
}

// ---------------------------------------------------------------------------
// Persistent flash attention, fp16 mma.sync (Q,K,V,P single fp16, 1-term).
// 3-stage KV pipeline, stage 2 overlays the dead Q tile. XOR-swizzled smem.
// Tiles (b,h,q0) pulled dynamically from a global counter.
// ---------------------------------------------------------------------------
#define AMB_OFF 49152                 // Q(16K@0 = stage2) + stages 0,1
#define ATTN_SMEM 49920               // + 3 x 256B mask stages
#define NT (SEQ / 64)
#define ATTN_TILES ((SEQ / 128) * NHEAD * BATCH)   // 1024

__global__ __launch_bounds__(256, 2) void attn_mma_kernel(
    const unsigned short* __restrict__ kqv16,
    const float* __restrict__ mask_bias,
    unsigned short* __restrict__ y16,
    unsigned int* __restrict__ ctr)
{
    extern __shared__ char smem_raw[];
    __shared__ int s_t;
    const uint32_t sb = smem_u32(smem_raw);
    const int tid  = threadIdx.x;
    const int lane = tid & 31;
    const int w    = tid >> 5;
    const int gr = lane >> 2;
    const int qq = lane & 3;
    const int lr = lane & 7;
    const int lh = (lane >> 3) & 1;
    const int lk = lane >> 4;

    auto stage_base = [&](int s) -> uint32_t {
        return sb + ((s == 2) ? 0u : (16384u + (uint32_t)s * 16384u));
    };

    for (;;) {
        __syncthreads();                       // previous tile done with smem
        if (tid == 0) s_t = (int)atomicAdd(ctr, 1u);
        __syncthreads();
        const int t = s_t;
        if (t >= ATTN_TILES) return;
        const int q0 = (t & 15) * 128;
        const int h  = (t >> 4) & 15;
        const int b  = t >> 8;

        const size_t rowbase = (size_t)b * SEQ * (3 * D_MODEL);
        const int koff = h * EDIM;             // chunk order (k, q, v)
        const int qoff = D_MODEL + h * EDIM;
        const int voff = 2 * D_MODEL + h * EDIM;
        const float* mbp = mask_bias + b * SEQ;

        auto load_kv = [&](int kt) {
            const int st = kt % 3;
            const uint32_t stg = stage_base(st);
            const int k0g = kt * 64;
#pragma unroll
            for (int i = 0; i < 2; i++) {
                const int chunk = tid + i * 256;    // 0..511
                const int r = chunk >> 3, c = chunk & 7;
                const uint32_t so = ASWZ(r, c);
                const size_t gk = rowbase + (size_t)(k0g + r) * (3 * D_MODEL) + koff + c * 8;
                const size_t gv = rowbase + (size_t)(k0g + r) * (3 * D_MODEL) + voff + c * 8;
                CP_ASYNC16(stg + so,        kqv16 + gk);
                CP_ASYNC16(stg + 8192 + so, kqv16 + gv);
            }
            if (tid < 16)
                CP_ASYNC16(sb + AMB_OFF + st * 256 + tid * 16, mbp + k0g + tid * 4);
        };

        // prologue: Q tile (fp16, 16KB @0) + kv0; then kv1
#pragma unroll
        for (int i = 0; i < 4; i++) {
            const int chunk = tid + i * 256;        // 0..1023
            const int r = chunk >> 3, c = chunk & 7;
            const size_t gq = rowbase + (size_t)(q0 + r) * (3 * D_MODEL) + qoff + c * 8;
            CP_ASYNC16(sb + ASWZ(r, c), kqv16 + gq);
        }
        load_kv(0);
        CP_COMMIT();
        load_kv(1);
        CP_COMMIT();

        float m0r = -INFINITY, m1r = -INFINITY, l0 = 0.0f, l1 = 0.0f;
        float O[8][4];
#pragma unroll
        for (int nb = 0; nb < 8; nb++)
#pragma unroll
            for (int q = 0; q < 4; q++) O[nb][q] = 0.0f;

        uint32_t qf[4][4];

        for (int kt = 0; kt < NT; kt++) {
            if (kt == NT - 1) CP_WAIT0(); else CP_WAIT1();
            __syncthreads();

            if (kt == 0) {
#pragma unroll
                for (int ks = 0; ks < 4; ks++) {
                    const int qrow = w * 16 + (lane & 15);
                    const uint32_t ra = ASWZ(qrow, ks * 2 + lk);
                    LDSM_X4(qf[ks][0], qf[ks][1], qf[ks][2], qf[ks][3], sb + ra);
                }
                __syncthreads();   // Q fully read before kv2 overlays it
            }
            if (kt + 2 < NT) { load_kv(kt + 2); CP_COMMIT(); }

            const int st = kt % 3;
            const uint32_t stg = stage_base(st);
            const uint32_t kbH = stg;
            const uint32_t vbH = stg + 8192;

            // ---- S = Q @ K^T (1-term fp16) ----
            float sacc[8][4];
#pragma unroll
            for (int nb = 0; nb < 8; nb++)
#pragma unroll
                for (int q = 0; q < 4; q++) sacc[nb][q] = 0.0f;

#pragma unroll
            for (int ks = 0; ks < 4; ks++) {
#pragma unroll
                for (int jp = 0; jp < 4; jp++) {
                    const int krow = jp * 16 + lr + lh * 8;
                    const uint32_t rb = ASWZ(krow, ks * 2 + lk);
                    uint32_t t0, t1, t2, t3;
                    uint32_t kh[2][2];
                    LDSM_X4(t0, t1, t2, t3, kbH + rb);
                    kh[0][0] = t0; kh[1][0] = t1; kh[0][1] = t2; kh[1][1] = t3;
                    MMA_F16(sacc[jp * 2 + 0], qf[ks], kh[0]);
                    MMA_F16(sacc[jp * 2 + 1], qf[ks], kh[1]);
                }
            }

            // ---- scale + mask + row max ----
            const float* mbt = (const float*)(smem_raw + AMB_OFF + st * 256);
            float tm0 = -INFINITY, tm1 = -INFINITY;
#pragma unroll
            for (int nb = 0; nb < 8; nb++) {
                float2 mv = *(const float2*)(mbt + nb * 8 + 2 * qq);
                sacc[nb][0] = fmaf(sacc[nb][0], 0.125f, mv.x);
                sacc[nb][1] = fmaf(sacc[nb][1], 0.125f, mv.y);
                sacc[nb][2] = fmaf(sacc[nb][2], 0.125f, mv.x);
                sacc[nb][3] = fmaf(sacc[nb][3], 0.125f, mv.y);
                tm0 = fmaxf(tm0, fmaxf(sacc[nb][0], sacc[nb][1]));
                tm1 = fmaxf(tm1, fmaxf(sacc[nb][2], sacc[nb][3]));
            }
            tm0 = fmaxf(tm0, __shfl_xor_sync(0xffffffffu, tm0, 1));
            tm0 = fmaxf(tm0, __shfl_xor_sync(0xffffffffu, tm0, 2));
            tm1 = fmaxf(tm1, __shfl_xor_sync(0xffffffffu, tm1, 1));
            tm1 = fmaxf(tm1, __shfl_xor_sync(0xffffffffu, tm1, 2));

            const float mn0 = fmaxf(m0r, tm0), mn1 = fmaxf(m1r, tm1);
            const float alpha0 = __expf(m0r - mn0), alpha1 = __expf(m1r - mn1);
            m0r = mn0; m1r = mn1;
#pragma unroll
            for (int nb = 0; nb < 8; nb++) {
                O[nb][0] *= alpha0; O[nb][1] *= alpha0;
                O[nb][2] *= alpha1; O[nb][3] *= alpha1;
            }

            // ---- interleaved: exp + fp16 P for step ks, then PV (1-term) ----
            float rs0 = 0.0f, rs1 = 0.0f;
#pragma unroll
            for (int ks = 0; ks < 4; ks++) {
                uint32_t ah[4];
                {
                    const int nb = 2 * ks;
                    float p0 = __expf(sacc[nb][0] - mn0);
                    float p1 = __expf(sacc[nb][1] - mn0);
                    float p2 = __expf(sacc[nb][2] - mn1);
                    float p3 = __expf(sacc[nb][3] - mn1);
                    rs0 += p0 + p1; rs1 += p2 + p3;
                    CVT_F16X2(ah[0], p0, p1);
                    CVT_F16X2(ah[1], p2, p3);
                }
                {
                    const int nb = 2 * ks + 1;
                    float p0 = __expf(sacc[nb][0] - mn0);
                    float p1 = __expf(sacc[nb][1] - mn0);
                    float p2 = __expf(sacc[nb][2] - mn1);
                    float p3 = __expf(sacc[nb][3] - mn1);
                    rs0 += p0 + p1; rs1 += p2 + p3;
                    CVT_F16X2(ah[2], p0, p1);
                    CVT_F16X2(ah[3], p2, p3);
                }
#pragma unroll
                for (int jp = 0; jp < 4; jp++) {
                    const int vrow = ks * 16 + lr + lh * 8;
                    const uint32_t ra = ASWZ(vrow, jp * 2 + lk);
                    uint32_t t0, t1, t2, t3;
                    uint32_t vb[2][2];
                    LDSM_X4_T(t0, t1, t2, t3, vbH + ra);
                    vb[0][0] = t0; vb[0][1] = t1; vb[1][0] = t2; vb[1][1] = t3;
                    MMA_F16(O[jp * 2 + 0], ah, vb[0]);
                    MMA_F16(O[jp * 2 + 1], ah, vb[1]);
                }
            }
            l0 = l0 * alpha0 + rs0;
            l1 = l1 * alpha1 + rs1;
        }

        // ---- epilogue: reduce l, normalize, write fp16 y ----
        l0 += __shfl_xor_sync(0xffffffffu, l0, 1);
        l0 += __shfl_xor_sync(0xffffffffu, l0, 2);
        l1 += __shfl_xor_sync(0xffffffffu, l1, 1);
        l1 += __shfl_xor_sync(0xffffffffu, l1, 2);
        const float inv0 = 1.0f / l0, inv1 = 1.0f / l1;

        const int r0 = q0 + w * 16 + gr;
        const int r1 = r0 + 8;
        const size_t o0 = ((size_t)(b * SEQ + r0)) * D_MODEL + h * EDIM + 2 * qq;
        const size_t o1 = ((size_t)(b * SEQ + r1)) * D_MODEL + h * EDIM + 2 * qq;
#pragma unroll
        for (int nb = 0; nb < 8; nb++) {
            uint32_t hh;
            CVT_F16X2(hh, O[nb][0] * inv0, O[nb][1] * inv0);
            *(uint32_t*)(y16 + o0 + nb * 8) = hh;
            CVT_F16X2(hh, O[nb][2] * inv1, O[nb][3] * inv1);
            *(uint32_t*)(y16 + o1 + nb * 8) = hh;
        }
    }
}

// ---------------------------------------------------------------------------
extern "C" void kernel_launch(void* const* d_in, const int* in_sizes, int n_in,
                              void* d_out, int out_size)
{
    const float* x     = (const float*)d_in[0];
    const void*  mask  = d_in[1];
    const float* Wqkv  = (const float*)d_in[2];
    const float* bqkv  = (const float*)d_in[3];
    const float* Wproj = (const float*)d_in[4];
    const float* bproj = (const float*)d_in[5];
    float* out = (float*)d_out;

    float *p_mb;
    unsigned int* p_ctr;
    unsigned short *p_x16, *p_wq16, *p_kqv16, *p_y16, *p_wp16;
    cudaGetSymbolAddress((void**)&p_mb,    g_mask_bias);
    cudaGetSymbolAddress((void**)&p_ctr,   g_ctr);
    cudaGetSymbolAddress((void**)&p_x16,   g_x16);
    cudaGetSymbolAddress((void**)&p_wq16,  g_wq16);
    cudaGetSymbolAddress((void**)&p_kqv16, g_kqv16);
    cudaGetSymbolAddress((void**)&p_y16,   g_y16);
    cudaGetSymbolAddress((void**)&p_wp16,  g_wp16);

    const int gemm_smem = 3 * STGB;                 // 98304
    cudaFuncSetAttribute(mma_gemm_f16_kernel<true>,
                         cudaFuncAttributeMaxDynamicSharedMemorySize, gemm_smem);
    cudaFuncSetAttribute(mma_gemm_f16_kernel<false>,
                         cudaFuncAttributeMaxDynamicSharedMemorySize, gemm_smem);
    cudaFuncSetAttribute(attn_mma_kernel,
                         cudaFuncAttributeMaxDynamicSharedMemorySize, ATTN_SMEM);

    // 1. mask -> additive bias (also zeroes tile counters each replay)
    mask_norm_kernel<<<(BATCH * SEQ + 255) / 256, 256>>>(mask, p_mb, p_ctr);

    // 2. fused fp16 converts (x, Wqkv, Wproj) — one launch
    cvt_all_kernel<<<2048, 256>>>(x, Wqkv, Wproj, p_x16, p_wq16, p_wp16);

    // 3. QKV projection (persistent): [8192,1024]@[3072,1024]^T, 1536 tiles
    mma_gemm_f16_kernel<true><<<NPCTA, 256, gemm_smem>>>(
        p_x16, p_wq16, bqkv, nullptr, p_kqv16,
        3 * D_MODEL, D_MODEL, 1536, 24, p_ctr + 0);

    // 4. Flash attention (persistent), 1024 tiles -> fp16 y
    attn_mma_kernel<<<NPCTA, 256, ATTN_SMEM>>>(p_kqv16, p_mb, p_y16, p_ctr + 1);

    // 5. Output projection (persistent): [8192,1024]@[1024,1024]^T, 512 tiles
    mma_gemm_f16_kernel<false><<<NPCTA, 256, gemm_smem>>>(
        p_y16, p_wp16, bproj, out, nullptr,
        D_MODEL, D_MODEL, 512, 8, p_ctr + 2);
}